// round 13
// baseline (speedup 1.0000x reference)
#include <cuda_runtime.h>

// PartialMatchingLoss via uniform-grid nearest neighbor.
// B=8 batches, M=4096 queries (partial), N=8192 points (completed), D=3.
//
// Grid: [-4,4]^3, h=0.25, 32^3 cells per batch, coords clamped (safe: clamping
// only mis-bins outliers into NEARER cells, so candidates are never missed and
// the ring lower bound stays valid). Cells hold up to CAP=32 u16 indices;
// overflow goes to a per-batch list scanned by every query (expected empty).
// Query expands Chebyshev rings; after finishing ring k, any unseen point is
// at distance > k*h, so stop when best <= k*h. Exact mins + fixed-order sums
// -> bit-deterministic regardless of atomic scheduling.

#define B_ 8
#define M_ 4096
#define N_ 8192
#define TOTAL_P (B_ * M_)            // 32768

#define GDIM 32
#define GLO  (-4.0f)
#define GH   0.25f
#define INVH 4.0f
#define CAP  32
#define CELLS_PER_B (GDIM * GDIM * GDIM)   // 32768
#define NCELLS (B_ * CELLS_PER_B)          // 262144
#define OVCAP 2048

#define KC_CTAS 256
#define KC_THREADS 128

// Static scratch (no allocation allowed). Rebuilt from scratch every launch:
// kA zeroes counts, kB fills, kC consumes and resets the ticket.
__device__ unsigned int   g_cellcnt[NCELLS];          // 1 MB
__device__ unsigned short g_bucket[NCELLS * CAP];     // 16.8 MB
__device__ float4         g_cpts[B_ * N_];            // 1 MB point cache
__device__ unsigned int   g_ovcnt[B_];
__device__ unsigned short g_ovlist[B_ * OVCAP];
__device__ float          g_blocksum[KC_CTAS];
__device__ unsigned int   g_tick;                     // zero-init; reset each launch

__device__ __forceinline__ int cell_of(float v) {
    int c = (int)floorf((v - GLO) * INVH);
    return min(max(c, 0), GDIM - 1);
}

// ---------------- kA: zero the per-launch build state ----------------
__global__ void kA_zero() {
    int i = blockIdx.x * blockDim.x + threadIdx.x;    // 65536 threads
    ((uint4*)g_cellcnt)[i] = make_uint4(0u, 0u, 0u, 0u);  // 65536*4 = NCELLS
    if (i < B_) g_ovcnt[i] = 0u;
}

// ---------------- kB: bin completed points ----------------
__global__ void kB_build(const float* __restrict__ completed) {
    int i = blockIdx.x * blockDim.x + threadIdx.x;    // 65536 = B_*N_
    int b = i >> 13;
    int m = i & (N_ - 1);
    const float* c = completed + (size_t)i * 3;
    float x = c[0], y = c[1], z = c[2];
    g_cpts[i] = make_float4(x, y, z, 0.0f);
    int cx = cell_of(x), cy = cell_of(y), cz = cell_of(z);
    int cid = b * CELLS_PER_B + (cz * GDIM + cy) * GDIM + cx;
    unsigned slot = atomicAdd(&g_cellcnt[cid], 1u);
    if (slot < CAP) {
        g_bucket[cid * CAP + slot] = (unsigned short)m;
    } else {
        unsigned o = atomicAdd(&g_ovcnt[b], 1u);
        if (o < OVCAP) g_ovlist[b * OVCAP + o] = (unsigned short)m;
    }
}

// ---------------- kC: query + reduction ----------------
__device__ __forceinline__ void visit_cell(int b, int cx, int cy, int cz,
                                           float px, float py, float pz,
                                           float& best2) {
    if ((unsigned)cx >= GDIM || (unsigned)cy >= GDIM || (unsigned)cz >= GDIM) return;
    int cid = b * CELLS_PER_B + (cz * GDIM + cy) * GDIM + cx;
    unsigned cnt = g_cellcnt[cid];
    if (cnt == 0u) return;
    if (cnt > CAP) cnt = CAP;
    const float4* cp = g_cpts + b * N_;
    const unsigned short* bk = g_bucket + cid * CAP;
    for (unsigned j0 = 0; j0 < cnt; j0 += 8) {
        uint4 w = *(const uint4*)(bk + j0);   // 8 u16 indices, 16B aligned
        unsigned idx8[8];
        idx8[0] = w.x & 0xFFFFu; idx8[1] = w.x >> 16;
        idx8[2] = w.y & 0xFFFFu; idx8[3] = w.y >> 16;
        idx8[4] = w.z & 0xFFFFu; idx8[5] = w.z >> 16;
        idx8[6] = w.w & 0xFFFFu; idx8[7] = w.w >> 16;
#pragma unroll
        for (int jj = 0; jj < 8; jj++) {
            if (j0 + (unsigned)jj < cnt) {
                float4 q = cp[idx8[jj]];
                float dx = px - q.x, dy = py - q.y, dz = pz - q.z;
                float d2 = fmaf(dx, dx, fmaf(dy, dy, dz * dz));
                best2 = fminf(best2, d2);
            }
        }
    }
}

__global__ void __launch_bounds__(KC_THREADS)
kC_query(const float* __restrict__ partial, float* __restrict__ out) {
    __shared__ float ssum[KC_THREADS];
    __shared__ int is_last;
    const int tid = threadIdx.x;
    const int pid = blockIdx.x * KC_THREADS + tid;   // pid = b*M + m
    const int b   = pid >> 12;

    const float* pp = partial + (size_t)pid * 3;
    float px = pp[0], py = pp[1], pz = pp[2];
    int qx = cell_of(px), qy = cell_of(py), qz = cell_of(pz);

    float best2 = 3.4e38f;

    // Overflow points (expected none; correctness safety net).
    {
        unsigned ov = g_ovcnt[b];
        if (ov > OVCAP) ov = OVCAP;
        for (unsigned o = 0; o < ov; o++) {
            float4 q = g_cpts[b * N_ + g_ovlist[b * OVCAP + o]];
            float dx = px - q.x, dy = py - q.y, dz = pz - q.z;
            best2 = fminf(best2, fmaf(dx, dx, fmaf(dy, dy, dz * dz)));
        }
    }

    // Ring 0.
    visit_cell(b, qx, qy, qz, px, py, pz, best2);

    // Expand rings; shell k visited via its 6 faces (no wasted interior).
    for (int k = 1; k < GDIM; k++) {
        for (int s = -k; s <= k; s += 2 * k) {        // z faces
            for (int dy = -k; dy <= k; dy++)
                for (int dx = -k; dx <= k; dx++)
                    visit_cell(b, qx + dx, qy + dy, qz + s, px, py, pz, best2);
        }
        for (int s = -k; s <= k; s += 2 * k) {        // y faces
            for (int dz = -k + 1; dz <= k - 1; dz++)
                for (int dx = -k; dx <= k; dx++)
                    visit_cell(b, qx + dx, qy + s, qz + dz, px, py, pz, best2);
        }
        for (int s = -k; s <= k; s += 2 * k) {        // x faces
            for (int dz = -k + 1; dz <= k - 1; dz++)
                for (int dy = -k + 1; dy <= k - 1; dy++)
                    visit_cell(b, qx + s, qy + dy, qz + dz, px, py, pz, best2);
        }
        float bound = (float)k * GH;
        if (best2 <= bound * bound) break;
    }

    float d = sqrtf(best2);

    // Deterministic reduction: block tree-sum, then the last-arriving CTA sums
    // the 256 block results in fixed order and resets the ticket.
    ssum[tid] = d;
    __syncthreads();
#pragma unroll
    for (int off = KC_THREADS / 2; off > 0; off >>= 1) {
        if (tid < off) ssum[tid] += ssum[tid + off];
        __syncthreads();
    }
    if (tid == 0) {
        g_blocksum[blockIdx.x] = ssum[0];
        __threadfence();
        unsigned int ticket = atomicAdd(&g_tick, 1u);
        is_last = (ticket == KC_CTAS - 1);
    }
    __syncthreads();

    if (is_last) {
        // All other CTAs' g_blocksum writes are visible (their fence precedes
        // the ticket that made us last).
        ssum[tid] = g_blocksum[tid] + g_blocksum[tid + KC_THREADS];
        __syncthreads();
#pragma unroll
        for (int off = KC_THREADS / 2; off > 0; off >>= 1) {
            if (tid < off) ssum[tid] += ssum[tid + off];
            __syncthreads();
        }
        if (tid == 0) {
            out[0] = ssum[0] * (1.0f / (float)TOTAL_P);
            g_tick = 0u;   // restore for the next graph replay
        }
    }
}

extern "C" void kernel_launch(void* const* d_in, const int* in_sizes, int n_in,
                              void* d_out, int out_size) {
    const float* completed = (const float*)d_in[0];  // (8, 8192, 3)
    const float* partial   = (const float*)d_in[1];  // (8, 4096, 3)
    if (n_in >= 2 && in_sizes[0] == B_ * M_ * 3 && in_sizes[1] == B_ * N_ * 3) {
        completed = (const float*)d_in[1];
        partial   = (const float*)d_in[0];
    }

    kA_zero<<<256, 256>>>();
    kB_build<<<256, 256>>>(completed);
    kC_query<<<KC_CTAS, KC_THREADS>>>(partial, (float*)d_out);
}

// round 14
// speedup vs baseline: 3.5256x; 3.5256x over previous
#include <cuda_runtime.h>

// PartialMatchingLoss via uniform-grid NN, WARP-PER-QUERY.
// B=8, M=4096 queries, N=8192 points, D=3.
//
// Grid [-4,4]^3, h=0.25, 32^3 cells/batch, coords clamped (safe: the shell
// bound uses clamped cell indices; coordinate gap >= (c-1)*h still holds).
// Buckets store the POINTS inline (float4, CAP=16/cell) so a cell visit is
// one count load + parallel point loads, no index indirection. Overflow
// points go to a per-batch list scanned by every query.
//
// One warp owns one query: shell-k cells are striped across lanes (no warp
// divergence on the walk; the break test uses the butterfly-reduced min so
// all lanes agree). After finishing cube k, any unseen point is >= k*h away,
// so stop when best2 <= (k*h)^2.
//
// Determinism: candidate mins are exact (fmin over a superset that always
// contains the true NN -> same value regardless of atomic fill order); all
// sums are fixed-order. State (counts, ticket) is re-zeroed every launch.

#define B_ 8
#define M_ 4096
#define N_ 8192
#define TOTAL_P (B_ * M_)            // 32768

#define GDIM 32
#define GLO  (-4.0f)
#define GH   0.25f
#define INVH 4.0f
#define CAP  16
#define CELLS_PER_B (GDIM * GDIM * GDIM)   // 32768
#define NCELLS (B_ * CELLS_PER_B)          // 262144
#define OVCAP 1024

#define KC_THREADS 256
#define QPC (KC_THREADS / 32)              // 8 queries per CTA
#define KC_CTAS (TOTAL_P / QPC)            // 4096

__device__ unsigned int g_cellcnt[NCELLS];          // 1 MB (kA zeroes)
__device__ float4       g_cbuck[NCELLS * CAP];      // 64 MB, points inline
__device__ unsigned int g_ovcnt[B_];
__device__ float4       g_ovpts[B_ * OVCAP];
__device__ float        g_blocksum[KC_CTAS];
__device__ unsigned int g_tick;                     // zero-init; reset each launch

__device__ __forceinline__ int cell_of(float v) {
    int c = (int)floorf((v - GLO) * INVH);
    return min(max(c, 0), GDIM - 1);
}

// ---------------- kA: zero build state (counts + overflow counters) --------
__global__ void kA_zero() {
    int i = blockIdx.x * blockDim.x + threadIdx.x;        // 65536 threads
    ((uint4*)g_cellcnt)[i] = make_uint4(0u, 0u, 0u, 0u);  // 65536*4 = NCELLS
    if (i < B_) g_ovcnt[i] = 0u;
}

// ---------------- kB: bin completed points (points stored inline) ----------
__global__ void kB_build(const float* __restrict__ completed) {
    int i = blockIdx.x * blockDim.x + threadIdx.x;        // 65536 = B_*N_
    int b = i >> 13;
    const float* c = completed + (size_t)i * 3;
    float x = c[0], y = c[1], z = c[2];
    int cid = b * CELLS_PER_B +
              (cell_of(z) * GDIM + cell_of(y)) * GDIM + cell_of(x);
    unsigned slot = atomicAdd(&g_cellcnt[cid], 1u);
    float4 p = make_float4(x, y, z, 0.0f);
    if (slot < CAP) {
        g_cbuck[(size_t)cid * CAP + slot] = p;
    } else {
        unsigned o = atomicAdd(&g_ovcnt[b], 1u);
        if (o < OVCAP) g_ovpts[b * OVCAP + o] = p;
    }
}

// ---------------- kC: warp-per-query search + fused reduction ---------------
__device__ __forceinline__ float warp_min(float v) {
#pragma unroll
    for (int off = 16; off > 0; off >>= 1)
        v = fminf(v, __shfl_xor_sync(0xFFFFFFFFu, v, off));
    return v;   // all lanes hold the min
}

__global__ void __launch_bounds__(KC_THREADS)
kC_query(const float* __restrict__ partial, float* __restrict__ out) {
    __shared__ float swarp[QPC];
    __shared__ int is_last;
    const int tid  = threadIdx.x;
    const int wid  = tid >> 5;
    const int lane = tid & 31;
    const int pid  = blockIdx.x * QPC + wid;   // query id = b*M + m
    const int b    = pid >> 12;

    const float* pp = partial + (size_t)pid * 3;   // broadcast across lanes
    const float px = pp[0], py = pp[1], pz = pp[2];
    const int qx = cell_of(px), qy = cell_of(py), qz = cell_of(pz);

    float best2 = 3.4e38f;

    // Overflow points (expected ~0; lanes stripe the list).
    {
        unsigned ov = min(g_ovcnt[b], (unsigned)OVCAP);
        for (unsigned o = lane; o < ov; o += 32) {
            float4 q = g_ovpts[b * OVCAP + o];
            float dx = px - q.x, dy = py - q.y, dz = pz - q.z;
            best2 = fminf(best2, fmaf(dx, dx, fmaf(dy, dy, dz * dz)));
        }
    }

    // Expanding cubes: k=1 visits the full 3x3x3 cube (incl. center); k>=2
    // visits only the shell. Lanes stripe the cell enumeration.
    float wbest = 3.4e38f;
    for (int k = 1; k <= GDIM; k++) {
        const int side = 2 * k + 1;
        const int s2   = side * side;
        const int tot  = s2 * side;
        for (int base = 0; base < tot; base += 32) {
            int idx = base + lane;
            if (idx < tot) {
                int dz = idx / s2;
                int rem = idx - dz * s2;
                int dy = rem / side;
                int dx = rem - dy * side;
                dx -= k; dy -= k; dz -= k;
                int amax = max(abs(dx), max(abs(dy), abs(dz)));
                if (k == 1 || amax == k) {       // shell only (k=1: full cube)
                    int cx = qx + dx, cy = qy + dy, cz = qz + dz;
                    if ((unsigned)cx < GDIM && (unsigned)cy < GDIM &&
                        (unsigned)cz < GDIM) {
                        int cid = b * CELLS_PER_B + (cz * GDIM + cy) * GDIM + cx;
                        unsigned cnt = min(g_cellcnt[cid], (unsigned)CAP);
                        if (cnt) {
                            const float4* bk = g_cbuck + (size_t)cid * CAP;
                            // First 4 slots: loads independent of cnt (stale
                            // data harmless -- fmin predicated by j<cnt).
                            float4 q0 = bk[0], q1 = bk[1], q2 = bk[2], q3 = bk[3];
                            float dxx, dyy, dzz, d2;
                            dxx = px - q0.x; dyy = py - q0.y; dzz = pz - q0.z;
                            d2 = fmaf(dxx, dxx, fmaf(dyy, dyy, dzz * dzz));
                            best2 = fminf(best2, d2);
                            if (cnt > 1) {
                                dxx = px - q1.x; dyy = py - q1.y; dzz = pz - q1.z;
                                d2 = fmaf(dxx, dxx, fmaf(dyy, dyy, dzz * dzz));
                                best2 = fminf(best2, d2);
                            }
                            if (cnt > 2) {
                                dxx = px - q2.x; dyy = py - q2.y; dzz = pz - q2.z;
                                d2 = fmaf(dxx, dxx, fmaf(dyy, dyy, dzz * dzz));
                                best2 = fminf(best2, d2);
                            }
                            if (cnt > 3) {
                                dxx = px - q3.x; dyy = py - q3.y; dzz = pz - q3.z;
                                d2 = fmaf(dxx, dxx, fmaf(dyy, dyy, dzz * dzz));
                                best2 = fminf(best2, d2);
                            }
                            for (unsigned j = 4; j < cnt; j++) {
                                float4 q = bk[j];
                                dxx = px - q.x; dyy = py - q.y; dzz = pz - q.z;
                                d2 = fmaf(dxx, dxx, fmaf(dyy, dyy, dzz * dzz));
                                best2 = fminf(best2, d2);
                            }
                        }
                    }
                }
            }
        }
        wbest = warp_min(best2);                 // all lanes agree
        float bound = (float)k * GH;
        if (wbest <= bound * bound) break;       // uniform branch
    }

    // Per-warp distance -> fixed-order CTA sum -> ticket-last final sum.
    if (lane == 0) swarp[wid] = sqrtf(wbest);
    __syncthreads();
    if (tid == 0) {
        float s = 0.0f;
#pragma unroll
        for (int i = 0; i < QPC; i++) s += swarp[i];      // fixed order
        g_blocksum[blockIdx.x] = s;
        __threadfence();
        unsigned int ticket = atomicAdd(&g_tick, 1u);
        is_last = (ticket == KC_CTAS - 1);
    }
    __syncthreads();

    if (is_last) {
        __shared__ float ssum[KC_THREADS];
        // All g_blocksum writes are visible (each CTA fenced before its ticket).
        float s = 0.0f;
#pragma unroll
        for (int i = 0; i < KC_CTAS / KC_THREADS; i++)    // 16 slots, fixed order
            s += g_blocksum[tid * (KC_CTAS / KC_THREADS) + i];
        ssum[tid] = s;
        __syncthreads();
#pragma unroll
        for (int off = KC_THREADS / 2; off > 0; off >>= 1) {
            if (tid < off) ssum[tid] += ssum[tid + off];
            __syncthreads();
        }
        if (tid == 0) {
            out[0] = ssum[0] * (1.0f / (float)TOTAL_P);
            g_tick = 0u;   // restore for the next graph replay
        }
    }
}

extern "C" void kernel_launch(void* const* d_in, const int* in_sizes, int n_in,
                              void* d_out, int out_size) {
    const float* completed = (const float*)d_in[0];  // (8, 8192, 3)
    const float* partial   = (const float*)d_in[1];  // (8, 4096, 3)
    if (n_in >= 2 && in_sizes[0] == B_ * M_ * 3 && in_sizes[1] == B_ * N_ * 3) {
        completed = (const float*)d_in[1];
        partial   = (const float*)d_in[0];
    }

    kA_zero<<<256, 256>>>();
    kB_build<<<256, 256>>>(completed);
    kC_query<<<KC_CTAS, KC_THREADS>>>(partial, (float*)d_out);
}

// round 15
// speedup vs baseline: 10.0267x; 2.8440x over previous
#include <cuda_runtime.h>

// PartialMatchingLoss via uniform-grid NN, warp-per-query, with a bounded
// walk (cube k<=2) and warp-striped brute-force fallback for unresolved
// (low-density tail) queries. B=8, M=4096 queries, N=8192 points, D=3.
//
// Grid [-4,4]^3, h=0.25, 32^3 cells/batch, coords clamped. Clamping is safe:
// it only moves BINS toward the center (understating cell distance ->
// conservative bound) and a clamped query's true coordinate is further from
// all interior cells than its clamped cell is.
// After finishing cube k, any unvisited point is >= k*h away, so the walk
// terminates when best2 <= (k*h)^2; otherwise (rare, ~1-2% tail queries) we
// scan all N points warp-striped -- exact, and it bounds the worst warp.
//
// Determinism: every min is exact over a candidate superset containing the
// true NN (atomic fill order cannot change the min); sums are fixed-order;
// counts/ticket re-zeroed every launch -> identical graph replays.

#define B_ 8
#define M_ 4096
#define N_ 8192
#define TOTAL_P (B_ * M_)            // 32768

#define GDIM 32
#define GLO  (-4.0f)
#define GH   0.25f
#define INVH 4.0f
#define CAP  16
#define CELLS_PER_B (GDIM * GDIM * GDIM)   // 32768
#define NCELLS (B_ * CELLS_PER_B)          // 262144
#define OVCAP 1024

#define KC_THREADS 256
#define QPC (KC_THREADS / 32)              // 8 queries per CTA
#define KC_CTAS (TOTAL_P / QPC)            // 4096

__device__ unsigned int g_cellcnt[NCELLS];          // 1 MB (kA zeroes)
__device__ float4       g_cbuck[NCELLS * CAP];      // 64 MB, points inline
__device__ float4       g_cpts[B_ * N_];            // 1 MB dense list (fallback)
__device__ unsigned int g_ovcnt[B_];
__device__ float4       g_ovpts[B_ * OVCAP];
__device__ float        g_blocksum[KC_CTAS];
__device__ unsigned int g_tick;                     // zero-init; reset each launch

__device__ __forceinline__ int cell_of(float v) {
    int c = (int)floorf((v - GLO) * INVH);
    return min(max(c, 0), GDIM - 1);
}

// ---------------- kA: zero build state ----------------
__global__ void kA_zero() {
    int i = blockIdx.x * blockDim.x + threadIdx.x;        // 65536 threads
    ((uint4*)g_cellcnt)[i] = make_uint4(0u, 0u, 0u, 0u);  // 65536*4 = NCELLS
    if (i < B_) g_ovcnt[i] = 0u;
}

// ---------------- kB: bin completed points + dense list ----------------
__global__ void kB_build(const float* __restrict__ completed) {
    int i = blockIdx.x * blockDim.x + threadIdx.x;        // 65536 = B_*N_
    int b = i >> 13;
    const float* c = completed + (size_t)i * 3;
    float x = c[0], y = c[1], z = c[2];
    float4 p = make_float4(x, y, z, 0.0f);
    g_cpts[i] = p;
    int cid = b * CELLS_PER_B +
              (cell_of(z) * GDIM + cell_of(y)) * GDIM + cell_of(x);
    unsigned slot = atomicAdd(&g_cellcnt[cid], 1u);
    if (slot < CAP) {
        g_cbuck[(size_t)cid * CAP + slot] = p;
    } else {
        unsigned o = atomicAdd(&g_ovcnt[b], 1u);
        if (o < OVCAP) g_ovpts[b * OVCAP + o] = p;
    }
}

// ---------------- kC: warp-per-query search + fused reduction ---------------
__device__ __forceinline__ float warp_min(float v) {
#pragma unroll
    for (int off = 16; off > 0; off >>= 1)
        v = fminf(v, __shfl_xor_sync(0xFFFFFFFFu, v, off));
    return v;   // all lanes hold the min
}

__device__ __forceinline__ void visit_cell(int b, int cx, int cy, int cz,
                                           float px, float py, float pz,
                                           float& best2) {
    if ((unsigned)cx >= GDIM || (unsigned)cy >= GDIM || (unsigned)cz >= GDIM)
        return;
    int cid = b * CELLS_PER_B + (cz * GDIM + cy) * GDIM + cx;
    unsigned cnt = min(g_cellcnt[cid], (unsigned)CAP);
    if (cnt == 0u) return;
    const float4* bk = g_cbuck + (size_t)cid * CAP;
    // First 4 slot loads are independent of cnt (stale data harmless: the
    // fmin is predicated by j < cnt), so they issue concurrently.
    float4 q0 = bk[0], q1 = bk[1], q2 = bk[2], q3 = bk[3];
    float dx, dy, dz, d2;
    dx = px - q0.x; dy = py - q0.y; dz = pz - q0.z;
    d2 = fmaf(dx, dx, fmaf(dy, dy, dz * dz));
    best2 = fminf(best2, d2);
    if (cnt > 1) {
        dx = px - q1.x; dy = py - q1.y; dz = pz - q1.z;
        best2 = fminf(best2, fmaf(dx, dx, fmaf(dy, dy, dz * dz)));
    }
    if (cnt > 2) {
        dx = px - q2.x; dy = py - q2.y; dz = pz - q2.z;
        best2 = fminf(best2, fmaf(dx, dx, fmaf(dy, dy, dz * dz)));
    }
    if (cnt > 3) {
        dx = px - q3.x; dy = py - q3.y; dz = pz - q3.z;
        best2 = fminf(best2, fmaf(dx, dx, fmaf(dy, dy, dz * dz)));
    }
    for (unsigned j = 4; j < cnt; j++) {
        float4 q = bk[j];
        dx = px - q.x; dy = py - q.y; dz = pz - q.z;
        best2 = fminf(best2, fmaf(dx, dx, fmaf(dy, dy, dz * dz)));
    }
}

__global__ void __launch_bounds__(KC_THREADS)
kC_query(const float* __restrict__ partial, float* __restrict__ out) {
    __shared__ float swarp[QPC];
    __shared__ int is_last;
    const int tid  = threadIdx.x;
    const int wid  = tid >> 5;
    const int lane = tid & 31;
    const int pid  = blockIdx.x * QPC + wid;   // query id = b*M + m
    const int b    = pid >> 12;

    const float* pp = partial + (size_t)pid * 3;   // broadcast across lanes
    const float px = pp[0], py = pp[1], pz = pp[2];
    const int qx = cell_of(px), qy = cell_of(py), qz = cell_of(pz);

    float best2 = 3.4e38f;

    // Overflow points (expected ~0; lanes stripe the list).
    {
        unsigned ov = min(g_ovcnt[b], (unsigned)OVCAP);
        for (unsigned o = lane; o < ov; o += 32) {
            float4 q = g_ovpts[b * OVCAP + o];
            float dx = px - q.x, dy = py - q.y, dz = pz - q.z;
            best2 = fminf(best2, fmaf(dx, dx, fmaf(dy, dy, dz * dz)));
        }
    }

    // Cube k=1: 27 cells on lanes 0..26, one pass.
    if (lane < 27) {
        int dx = lane % 3 - 1;
        int dy = (lane / 3) % 3 - 1;
        int dz = lane / 9 - 1;
        visit_cell(b, qx + dx, qy + dy, qz + dz, px, py, pz, best2);
    }
    float wbest = warp_min(best2);

    if (wbest > GH * GH) {
        // Shell k=2: the 98 cells of the 5^3 cube with Chebyshev radius 2.
        for (int base = 0; base < 125; base += 32) {
            int idx = base + lane;
            if (idx < 125) {
                int dz = idx / 25 - 2;
                int dy = (idx / 5) % 5 - 2;
                int dx = idx % 5 - 2;
                if (max(abs(dx), max(abs(dy), abs(dz))) == 2)
                    visit_cell(b, qx + dx, qy + dy, qz + dz, px, py, pz, best2);
            }
        }
        wbest = warp_min(best2);

        if (wbest > 4.0f * GH * GH) {
            // Fallback: exact warp-striped scan of all N points (rare).
            const float4* cp = g_cpts + b * N_;
            for (int i0 = 0; i0 < N_; i0 += 128) {
                float4 a0 = cp[i0 + lane];
                float4 a1 = cp[i0 + 32 + lane];
                float4 a2 = cp[i0 + 64 + lane];
                float4 a3 = cp[i0 + 96 + lane];
                float dx, dy, dz;
                dx = px - a0.x; dy = py - a0.y; dz = pz - a0.z;
                best2 = fminf(best2, fmaf(dx, dx, fmaf(dy, dy, dz * dz)));
                dx = px - a1.x; dy = py - a1.y; dz = pz - a1.z;
                best2 = fminf(best2, fmaf(dx, dx, fmaf(dy, dy, dz * dz)));
                dx = px - a2.x; dy = py - a2.y; dz = pz - a2.z;
                best2 = fminf(best2, fmaf(dx, dx, fmaf(dy, dy, dz * dz)));
                dx = px - a3.x; dy = py - a3.y; dz = pz - a3.z;
                best2 = fminf(best2, fmaf(dx, dx, fmaf(dy, dy, dz * dz)));
            }
            wbest = warp_min(best2);
        }
    }

    // Per-warp distance -> fixed-order CTA sum -> ticket-last final sum.
    if (lane == 0) swarp[wid] = sqrtf(wbest);
    __syncthreads();
    if (tid == 0) {
        float s = 0.0f;
#pragma unroll
        for (int i = 0; i < QPC; i++) s += swarp[i];      // fixed order
        g_blocksum[blockIdx.x] = s;
        __threadfence();
        unsigned int ticket = atomicAdd(&g_tick, 1u);
        is_last = (ticket == KC_CTAS - 1);
    }
    __syncthreads();

    if (is_last) {
        __shared__ float ssum[KC_THREADS];
        // All g_blocksum writes are visible (each CTA fenced before its ticket).
        float s = 0.0f;
#pragma unroll
        for (int i = 0; i < KC_CTAS / KC_THREADS; i++)    // 16 slots, fixed order
            s += g_blocksum[tid * (KC_CTAS / KC_THREADS) + i];
        ssum[tid] = s;
        __syncthreads();
#pragma unroll
        for (int off = KC_THREADS / 2; off > 0; off >>= 1) {
            if (tid < off) ssum[tid] += ssum[tid + off];
            __syncthreads();
        }
        if (tid == 0) {
            out[0] = ssum[0] * (1.0f / (float)TOTAL_P);
            g_tick = 0u;   // restore for the next graph replay
        }
    }
}

extern "C" void kernel_launch(void* const* d_in, const int* in_sizes, int n_in,
                              void* d_out, int out_size) {
    const float* completed = (const float*)d_in[0];  // (8, 8192, 3)
    const float* partial   = (const float*)d_in[1];  // (8, 4096, 3)
    if (n_in >= 2 && in_sizes[0] == B_ * M_ * 3 && in_sizes[1] == B_ * N_ * 3) {
        completed = (const float*)d_in[1];
        partial   = (const float*)d_in[0];
    }

    kA_zero<<<256, 256>>>();
    kB_build<<<256, 256>>>(completed);
    kC_query<<<KC_CTAS, KC_THREADS>>>(partial, (float*)d_out);
}